// round 3
// baseline (speedup 1.0000x reference)
#include <cuda_runtime.h>

#define BB   8
#define NN   4096
#define CC   6
#define KNBR 16
#define H1   64
#define H2   128

static __device__ int   g_nbr[BB * NN * KNBR];          // 2 MB
static __device__ float g_x1 [BB * NN * H1];            // 8 MB

// ---------------------------------------------------------------------------
// Kernel 1: exact KNN (k=16) per batch. Replicates reference arithmetic:
//   sq   = (x*x + y*y) + z*z                       (rounded per op)
//   dot  = fma(z, z', fma(y, y', x*x'))            (ascending fma chain)
//   d2   = (sq_i + sq_j) - 2*dot   == fma(dot,-2, sq_i+sq_j)  (2*dot exact)
// Strict '<' everywhere -> lower index wins ties, matching lax.top_k.
// ---------------------------------------------------------------------------
__global__ void knn_kernel(const float* __restrict__ feats) {
    extern __shared__ float smem_f[];
    float4* sp = (float4*)smem_f;                       // [NN] : x,y,z,sq

    const int b = blockIdx.y;
    const float* fb = feats + (size_t)b * NN * CC;
    for (int j = threadIdx.x; j < NN; j += blockDim.x) {
        float x = fb[j * CC + 0];
        float y = fb[j * CC + 1];
        float z = fb[j * CC + 2];
        float sq = __fadd_rn(__fadd_rn(__fmul_rn(x, x), __fmul_rn(y, y)),
                             __fmul_rn(z, z));
        sp[j] = make_float4(x, y, z, sq);
    }
    __syncthreads();

    const int i = blockIdx.x * blockDim.x + threadIdx.x;
    const float4 q = sp[i];

    float bd[KNBR];
    int   bi[KNBR];
#pragma unroll
    for (int s = 0; s < KNBR; ++s) { bd[s] = 3.402823466e38f; bi[s] = 0; }

#pragma unroll 4
    for (int j = 0; j < NN; ++j) {
        float4 p = sp[j];
        float dot = __fmaf_rn(q.z, p.z, __fmaf_rn(q.y, p.y, __fmul_rn(q.x, p.x)));
        float d2  = __fmaf_rn(dot, -2.0f, __fadd_rn(q.w, p.w));
        if (d2 < bd[KNBR - 1] && j != i) {
            float cd = d2; int ci = j;
#pragma unroll
            for (int s = 0; s < KNBR; ++s) {
                bool sw = cd < bd[s];
                float td = bd[s]; int ti = bi[s];
                if (sw) { bd[s] = cd; bi[s] = ci; cd = td; ci = ti; }
            }
        }
    }

    const int base = (b * NN + i) * KNBR;
#pragma unroll
    for (int s = 0; s < KNBR; ++s) g_nbr[base + s] = bi[s];
}

// ---------------------------------------------------------------------------
// Kernel 2: x1 = relu( ((sum_{j in nbr(i)} feats[j]) + feats[i]) @ W1 * inv + b1 )
// (aggregation moved before the linear layer by linearity)
// Whole-batch feats staged in smem (96 KB).
// ---------------------------------------------------------------------------
__global__ void layer1_kernel(const float* __restrict__ feats,
                              const float* __restrict__ W1,
                              const float* __restrict__ b1) {
    extern __shared__ float smem_f[];
    float* fs  = smem_f;                // NN*CC
    float* W1s = fs + NN * CC;          // CC*H1
    float* b1s = W1s + CC * H1;         // H1

    const int b = blockIdx.y;
    const float* fb = feats + (size_t)b * NN * CC;
    for (int t = threadIdx.x; t < NN * CC; t += blockDim.x) fs[t] = fb[t];
    for (int t = threadIdx.x; t < CC * H1; t += blockDim.x) W1s[t] = W1[t];
    if (threadIdx.x < H1) b1s[threadIdx.x] = b1[threadIdx.x];
    __syncthreads();

    const int i = blockIdx.x * blockDim.x + threadIdx.x;

    float s[CC];
#pragma unroll
    for (int c = 0; c < CC; ++c) s[c] = fs[i * CC + c];

    const int* nb = g_nbr + (size_t)(b * NN + i) * KNBR;
#pragma unroll
    for (int n = 0; n < KNBR; ++n) {
        int j = nb[n];
#pragma unroll
        for (int c = 0; c < CC; ++c) s[c] += fs[j * CC + c];
    }

    float* xo = g_x1 + (size_t)(b * NN + i) * H1;
    const float inv = 1.0f / 17.0f;
#pragma unroll 4
    for (int c = 0; c < H1; ++c) {
        float a = s[0] * W1s[c];
#pragma unroll
        for (int kk = 1; kk < CC; ++kk) a = fmaf(s[kk], W1s[kk * H1 + c], a);
        xo[c] = fmaxf(fmaf(a, inv, b1s[c]), 0.0f);
    }
}

// ---------------------------------------------------------------------------
// Kernel 3 (fused): per 32-point tile:
//   s1  = gather-sum of x1 over {i} U nbr(i)              (from L2)
//   x2  = relu( s1 @ W2 * inv + b2 )                      (smem)
//   out = x2 @ Wf + bf                                    (global)
// W2 + Wf resident in smem; 4 points x 4 cols register blocking, float4 LDS.
// ---------------------------------------------------------------------------
__device__ __forceinline__ float f4get(float4 v, int kk) {
    return kk == 0 ? v.x : kk == 1 ? v.y : kk == 2 ? v.z : v.w;
}

#define PTS 32

__global__ __launch_bounds__(256, 1)
void layer2_kernel(const float* __restrict__ W2,
                   const float* __restrict__ b2,
                   const float* __restrict__ Wf,
                   const float* __restrict__ bf,
                   float* __restrict__ out) {
    extern __shared__ float smem_f[];
    float* W2s = smem_f;                 // 64*128
    float* Wfs = W2s + H1 * H2;          // 128*128
    float* b2s = Wfs + H2 * H2;          // 128
    float* bfs = b2s + H2;               // 128
    float* s1  = bfs + H2;               // 32*64
    float* x2s = s1 + PTS * H1;          // 32*128

    for (int t = threadIdx.x; t < H1 * H2; t += blockDim.x) W2s[t] = W2[t];
    for (int t = threadIdx.x; t < H2 * H2; t += blockDim.x) Wfs[t] = Wf[t];
    if (threadIdx.x < H2) { b2s[threadIdx.x] = b2[threadIdx.x]; bfs[threadIdx.x] = bf[threadIdx.x]; }

    const int lane = threadIdx.x & 31;
    const int warp = threadIdx.x >> 5;              // 8 warps
    const int gp0  = blockIdx.x * PTS;              // global point base
    const int b    = gp0 >> 12;                     // / 4096 (PTS divides NN)
    const float* x1b = g_x1 + (size_t)b * NN * H1;

    // phase 1: gather-sum x1 -> s1 (warp w handles points 4w..4w+3)
#pragma unroll
    for (int pp = 0; pp < 4; ++pp) {
        int p  = warp * 4 + pp;
        int gi = gp0 + p;
        int li = gi & (NN - 1);
        const int* nb = g_nbr + (size_t)gi * KNBR;
        const float2* row = (const float2*)(x1b + (size_t)li * H1);
        float2 v = row[lane];
        float a0 = v.x, a1 = v.y;
#pragma unroll
        for (int n = 0; n < KNBR; ++n) {
            int j = nb[n];
            float2 w = ((const float2*)(x1b + (size_t)j * H1))[lane];
            a0 += w.x; a1 += w.y;
        }
        ((float2*)(s1 + p * H1))[lane] = make_float2(a0, a1);
    }
    __syncthreads();

    const float inv = 1.0f / 17.0f;

    // phase 2: x2 = relu(s1 @ W2 * inv + b2); cols lane*4..lane*4+3
    {
        float acc[4][4];
#pragma unroll
        for (int pp = 0; pp < 4; ++pp)
#pragma unroll
            for (int cc = 0; cc < 4; ++cc) acc[pp][cc] = 0.0f;

#pragma unroll 4
        for (int k = 0; k < H1; k += 4) {
            float4 xv[4];
#pragma unroll
            for (int pp = 0; pp < 4; ++pp)
                xv[pp] = *(const float4*)&s1[(warp * 4 + pp) * H1 + k];
#pragma unroll
            for (int kk = 0; kk < 4; ++kk) {
                float4 w = *(const float4*)&W2s[(k + kk) * H2 + lane * 4];
#pragma unroll
                for (int pp = 0; pp < 4; ++pp) {
                    float xs = f4get(xv[pp], kk);
                    acc[pp][0] = fmaf(xs, w.x, acc[pp][0]);
                    acc[pp][1] = fmaf(xs, w.y, acc[pp][1]);
                    acc[pp][2] = fmaf(xs, w.z, acc[pp][2]);
                    acc[pp][3] = fmaf(xs, w.w, acc[pp][3]);
                }
            }
        }
#pragma unroll
        for (int pp = 0; pp < 4; ++pp) {
            float4 r;
            r.x = fmaxf(fmaf(acc[pp][0], inv, b2s[lane * 4 + 0]), 0.0f);
            r.y = fmaxf(fmaf(acc[pp][1], inv, b2s[lane * 4 + 1]), 0.0f);
            r.z = fmaxf(fmaf(acc[pp][2], inv, b2s[lane * 4 + 2]), 0.0f);
            r.w = fmaxf(fmaf(acc[pp][3], inv, b2s[lane * 4 + 3]), 0.0f);
            *(float4*)&x2s[(warp * 4 + pp) * H2 + lane * 4] = r;
        }
    }
    __syncthreads();

    // phase 3: out = x2 @ Wf + bf
    {
        float acc[4][4];
#pragma unroll
        for (int pp = 0; pp < 4; ++pp)
#pragma unroll
            for (int cc = 0; cc < 4; ++cc) acc[pp][cc] = 0.0f;

#pragma unroll 4
        for (int k = 0; k < H2; k += 4) {
            float4 xv[4];
#pragma unroll
            for (int pp = 0; pp < 4; ++pp)
                xv[pp] = *(const float4*)&x2s[(warp * 4 + pp) * H2 + k];
#pragma unroll
            for (int kk = 0; kk < 4; ++kk) {
                float4 w = *(const float4*)&Wfs[(k + kk) * H2 + lane * 4];
#pragma unroll
                for (int pp = 0; pp < 4; ++pp) {
                    float xs = f4get(xv[pp], kk);
                    acc[pp][0] = fmaf(xs, w.x, acc[pp][0]);
                    acc[pp][1] = fmaf(xs, w.y, acc[pp][1]);
                    acc[pp][2] = fmaf(xs, w.z, acc[pp][2]);
                    acc[pp][3] = fmaf(xs, w.w, acc[pp][3]);
                }
            }
        }
#pragma unroll
        for (int pp = 0; pp < 4; ++pp) {
            int gi = gp0 + warp * 4 + pp;
            float4 r;
            r.x = acc[pp][0] + bfs[lane * 4 + 0];
            r.y = acc[pp][1] + bfs[lane * 4 + 1];
            r.z = acc[pp][2] + bfs[lane * 4 + 2];
            r.w = acc[pp][3] + bfs[lane * 4 + 3];
            *(float4*)&out[(size_t)gi * H2 + lane * 4] = r;
        }
    }
}

// ---------------------------------------------------------------------------
extern "C" void kernel_launch(void* const* d_in, const int* in_sizes, int n_in,
                              void* d_out, int out_size) {
    const float* feats = (const float*)d_in[0];
    const float* W1    = (const float*)d_in[1];
    const float* b1    = (const float*)d_in[2];
    const float* W2    = (const float*)d_in[3];
    const float* b2    = (const float*)d_in[4];
    const float* Wf    = (const float*)d_in[5];
    const float* bf    = (const float*)d_in[6];
    float* out = (float*)d_out;

    const int smem_knn = NN * (int)sizeof(float4);                       // 64 KB
    const int smem_l1  = (NN * CC + CC * H1 + H1) * (int)sizeof(float);  // ~98 KB
    const int smem_l2  = (H1 * H2 + H2 * H2 + 2 * H2 + PTS * H1 + PTS * H2)
                         * (int)sizeof(float);                           // ~121 KB

    cudaFuncSetAttribute(knn_kernel,    cudaFuncAttributeMaxDynamicSharedMemorySize, smem_knn);
    cudaFuncSetAttribute(layer1_kernel, cudaFuncAttributeMaxDynamicSharedMemorySize, smem_l1);
    cudaFuncSetAttribute(layer2_kernel, cudaFuncAttributeMaxDynamicSharedMemorySize, smem_l2);

    dim3 gBN(NN / 256, BB);
    knn_kernel   <<<gBN, 256, smem_knn>>>(feats);
    layer1_kernel<<<gBN, 256, smem_l1>>>(feats, W1, b1);
    layer2_kernel<<<(BB * NN) / PTS, 256, smem_l2>>>(W2, b2, Wf, bf, out);
}

// round 4
// speedup vs baseline: 1.8085x; 1.8085x over previous
#include <cuda_runtime.h>

#define BB   8
#define NN   4096
#define CC   6
#define KNBR 16
#define H1   64
#define H2   128

static __device__ int   g_nbr[BB * NN * KNBR];          // 2 MB
static __device__ float g_x1 [BB * NN * H1];            // 8 MB

// ---------------------------------------------------------------------------
// Kernel 1: exact KNN (k=16), warp-per-query with lane-distributed sorted
// top-16. Key = (ordered_uint(d2) << 32) | idx  -> exact tie-break by lower
// index, insertion-order independent. Distance arithmetic bit-matches the
// reference: d2 = fma(dot, -2, sq_i + sq_j), dot = ascending fma chain.
// ---------------------------------------------------------------------------
__global__ __launch_bounds__(512)
void knn_kernel(const float* __restrict__ feats) {
    extern __shared__ float smem_f[];
    float4* sp = (float4*)smem_f;                       // [NN] : x,y,z,sq

    const int b = blockIdx.y;
    const float* fb = feats + (size_t)b * NN * CC;
    for (int j = threadIdx.x; j < NN; j += blockDim.x) {
        float x = fb[j * CC + 0];
        float y = fb[j * CC + 1];
        float z = fb[j * CC + 2];
        float sq = __fadd_rn(__fadd_rn(__fmul_rn(x, x), __fmul_rn(y, y)),
                             __fmul_rn(z, z));
        sp[j] = make_float4(x, y, z, sq);
    }
    __syncthreads();

    const int lane = threadIdx.x & 31;
    const int wid  = threadIdx.x >> 5;                  // 16 warps
    const int i    = blockIdx.x * 16 + wid;             // query index
    const float4 q = sp[i];
    const int ibase = i & ~31;
    const int ilane = i & 31;

    unsigned long long key = ~0ULL;                     // lane-distributed list
    unsigned tau = 0xFFFFFFFFu;                         // hi-word of lane 15

#pragma unroll 2
    for (int jb = 0; jb < NN; jb += 32) {
        float4 p = sp[jb + lane];
        float dot = __fmaf_rn(q.z, p.z, __fmaf_rn(q.y, p.y, __fmul_rn(q.x, p.x)));
        float d2  = __fmaf_rn(dot, -2.0f, __fadd_rn(q.w, p.w));
        int fbits = __float_as_int(d2);
        unsigned cu = (unsigned)fbits ^ (unsigned)((fbits >> 31) | 0x80000000);
        if (jb == ibase && lane == ilane) cu = 0xFFFFFFFFu;   // exclude self
        unsigned long long ck =
            ((unsigned long long)cu << 32) | (unsigned)(jb + lane);

        unsigned bal = __ballot_sync(0xFFFFFFFFu, cu <= tau);
        while (bal) {
            int src = __ffs(bal) - 1;
            bal &= bal - 1;
            unsigned long long nk = __shfl_sync(0xFFFFFFFFu, ck, src);
            unsigned m = __ballot_sync(0xFFFFFFFFu, nk < key);  // suffix mask
            unsigned long long up = __shfl_up_sync(0xFFFFFFFFu, key, 1);
            if (m) {
                int pos = __ffs(m) - 1;
                if (lane >= pos) key = (lane == pos) ? nk : up;
            }
            tau = (unsigned)(__shfl_sync(0xFFFFFFFFu, key, 15) >> 32);
            if (bal) bal &= __ballot_sync(0xFFFFFFFFu, cu <= tau);
        }
    }

    if (lane < KNBR)
        g_nbr[(b * NN + i) * KNBR + lane] = (int)(unsigned)key;
}

// ---------------------------------------------------------------------------
// Kernel 2: x1 = relu( ((sum_{j in nbr(i)} feats[j]) + feats[i]) @ W1 * inv + b1 )
// ---------------------------------------------------------------------------
__global__ void layer1_kernel(const float* __restrict__ feats,
                              const float* __restrict__ W1,
                              const float* __restrict__ b1) {
    extern __shared__ float smem_f[];
    float* fs  = smem_f;                // NN*CC
    float* W1s = fs + NN * CC;          // CC*H1
    float* b1s = W1s + CC * H1;         // H1

    const int b = blockIdx.y;
    const float* fb = feats + (size_t)b * NN * CC;
    for (int t = threadIdx.x; t < NN * CC; t += blockDim.x) fs[t] = fb[t];
    for (int t = threadIdx.x; t < CC * H1; t += blockDim.x) W1s[t] = W1[t];
    if (threadIdx.x < H1) b1s[threadIdx.x] = b1[threadIdx.x];
    __syncthreads();

    const int i = blockIdx.x * blockDim.x + threadIdx.x;

    float s[CC];
#pragma unroll
    for (int c = 0; c < CC; ++c) s[c] = fs[i * CC + c];

    const int* nb = g_nbr + (size_t)(b * NN + i) * KNBR;
#pragma unroll
    for (int n = 0; n < KNBR; ++n) {
        int j = nb[n];
#pragma unroll
        for (int c = 0; c < CC; ++c) s[c] += fs[j * CC + c];
    }

    float* xo = g_x1 + (size_t)(b * NN + i) * H1;
    const float inv = 1.0f / 17.0f;
#pragma unroll 4
    for (int c = 0; c < H1; ++c) {
        float a = s[0] * W1s[c];
#pragma unroll
        for (int kk = 1; kk < CC; ++kk) a = fmaf(s[kk], W1s[kk * H1 + c], a);
        xo[c] = fmaxf(fmaf(a, inv, b1s[c]), 0.0f);
    }
}

// ---------------------------------------------------------------------------
// Kernel 3 (fused): gather-sum x1 -> x2 = relu(.@W2*inv+b2) -> out = x2@Wf+bf
// ---------------------------------------------------------------------------
__device__ __forceinline__ float f4get(float4 v, int kk) {
    return kk == 0 ? v.x : kk == 1 ? v.y : kk == 2 ? v.z : v.w;
}

#define PTS 32

__global__ __launch_bounds__(256, 1)
void layer2_kernel(const float* __restrict__ W2,
                   const float* __restrict__ b2,
                   const float* __restrict__ Wf,
                   const float* __restrict__ bf,
                   float* __restrict__ out) {
    extern __shared__ float smem_f[];
    float* W2s = smem_f;                 // 64*128
    float* Wfs = W2s + H1 * H2;          // 128*128
    float* b2s = Wfs + H2 * H2;          // 128
    float* bfs = b2s + H2;               // 128
    float* s1  = bfs + H2;               // 32*64
    float* x2s = s1 + PTS * H1;          // 32*128

    for (int t = threadIdx.x; t < H1 * H2; t += blockDim.x) W2s[t] = W2[t];
    for (int t = threadIdx.x; t < H2 * H2; t += blockDim.x) Wfs[t] = Wf[t];
    if (threadIdx.x < H2) { b2s[threadIdx.x] = b2[threadIdx.x]; bfs[threadIdx.x] = bf[threadIdx.x]; }

    const int lane = threadIdx.x & 31;
    const int warp = threadIdx.x >> 5;              // 8 warps
    const int gp0  = blockIdx.x * PTS;              // global point base
    const int b    = gp0 >> 12;                     // / 4096
    const float* x1b = g_x1 + (size_t)b * NN * H1;

    // phase 1: gather-sum x1 -> s1
#pragma unroll
    for (int pp = 0; pp < 4; ++pp) {
        int p  = warp * 4 + pp;
        int gi = gp0 + p;
        int li = gi & (NN - 1);
        const int* nb = g_nbr + (size_t)gi * KNBR;
        const float2* row = (const float2*)(x1b + (size_t)li * H1);
        float2 v = row[lane];
        float a0 = v.x, a1 = v.y;
#pragma unroll
        for (int n = 0; n < KNBR; ++n) {
            int j = nb[n];
            float2 w = ((const float2*)(x1b + (size_t)j * H1))[lane];
            a0 += w.x; a1 += w.y;
        }
        ((float2*)(s1 + p * H1))[lane] = make_float2(a0, a1);
    }
    __syncthreads();

    const float inv = 1.0f / 17.0f;

    // phase 2: x2 = relu(s1 @ W2 * inv + b2)
    {
        float acc[4][4];
#pragma unroll
        for (int pp = 0; pp < 4; ++pp)
#pragma unroll
            for (int cc = 0; cc < 4; ++cc) acc[pp][cc] = 0.0f;

#pragma unroll 4
        for (int k = 0; k < H1; k += 4) {
            float4 xv[4];
#pragma unroll
            for (int pp = 0; pp < 4; ++pp)
                xv[pp] = *(const float4*)&s1[(warp * 4 + pp) * H1 + k];
#pragma unroll
            for (int kk = 0; kk < 4; ++kk) {
                float4 w = *(const float4*)&W2s[(k + kk) * H2 + lane * 4];
#pragma unroll
                for (int pp = 0; pp < 4; ++pp) {
                    float xs = f4get(xv[pp], kk);
                    acc[pp][0] = fmaf(xs, w.x, acc[pp][0]);
                    acc[pp][1] = fmaf(xs, w.y, acc[pp][1]);
                    acc[pp][2] = fmaf(xs, w.z, acc[pp][2]);
                    acc[pp][3] = fmaf(xs, w.w, acc[pp][3]);
                }
            }
        }
#pragma unroll
        for (int pp = 0; pp < 4; ++pp) {
            float4 r;
            r.x = fmaxf(fmaf(acc[pp][0], inv, b2s[lane * 4 + 0]), 0.0f);
            r.y = fmaxf(fmaf(acc[pp][1], inv, b2s[lane * 4 + 1]), 0.0f);
            r.z = fmaxf(fmaf(acc[pp][2], inv, b2s[lane * 4 + 2]), 0.0f);
            r.w = fmaxf(fmaf(acc[pp][3], inv, b2s[lane * 4 + 3]), 0.0f);
            *(float4*)&x2s[(warp * 4 + pp) * H2 + lane * 4] = r;
        }
    }
    __syncthreads();

    // phase 3: out = x2 @ Wf + bf
    {
        float acc[4][4];
#pragma unroll
        for (int pp = 0; pp < 4; ++pp)
#pragma unroll
            for (int cc = 0; cc < 4; ++cc) acc[pp][cc] = 0.0f;

#pragma unroll 4
        for (int k = 0; k < H2; k += 4) {
            float4 xv[4];
#pragma unroll
            for (int pp = 0; pp < 4; ++pp)
                xv[pp] = *(const float4*)&x2s[(warp * 4 + pp) * H2 + k];
#pragma unroll
            for (int kk = 0; kk < 4; ++kk) {
                float4 w = *(const float4*)&Wfs[(k + kk) * H2 + lane * 4];
#pragma unroll
                for (int pp = 0; pp < 4; ++pp) {
                    float xs = f4get(xv[pp], kk);
                    acc[pp][0] = fmaf(xs, w.x, acc[pp][0]);
                    acc[pp][1] = fmaf(xs, w.y, acc[pp][1]);
                    acc[pp][2] = fmaf(xs, w.z, acc[pp][2]);
                    acc[pp][3] = fmaf(xs, w.w, acc[pp][3]);
                }
            }
        }
#pragma unroll
        for (int pp = 0; pp < 4; ++pp) {
            int gi = gp0 + warp * 4 + pp;
            float4 r;
            r.x = acc[pp][0] + bfs[lane * 4 + 0];
            r.y = acc[pp][1] + bfs[lane * 4 + 1];
            r.z = acc[pp][2] + bfs[lane * 4 + 2];
            r.w = acc[pp][3] + bfs[lane * 4 + 3];
            *(float4*)&out[(size_t)gi * H2 + lane * 4] = r;
        }
    }
}

// ---------------------------------------------------------------------------
extern "C" void kernel_launch(void* const* d_in, const int* in_sizes, int n_in,
                              void* d_out, int out_size) {
    const float* feats = (const float*)d_in[0];
    const float* W1    = (const float*)d_in[1];
    const float* b1    = (const float*)d_in[2];
    const float* W2    = (const float*)d_in[3];
    const float* b2    = (const float*)d_in[4];
    const float* Wf    = (const float*)d_in[5];
    const float* bf    = (const float*)d_in[6];
    float* out = (float*)d_out;

    const int smem_knn = NN * (int)sizeof(float4);                       // 64 KB
    const int smem_l1  = (NN * CC + CC * H1 + H1) * (int)sizeof(float);  // ~98 KB
    const int smem_l2  = (H1 * H2 + H2 * H2 + 2 * H2 + PTS * H1 + PTS * H2)
                         * (int)sizeof(float);                           // ~121 KB

    cudaFuncSetAttribute(knn_kernel,    cudaFuncAttributeMaxDynamicSharedMemorySize, smem_knn);
    cudaFuncSetAttribute(layer1_kernel, cudaFuncAttributeMaxDynamicSharedMemorySize, smem_l1);
    cudaFuncSetAttribute(layer2_kernel, cudaFuncAttributeMaxDynamicSharedMemorySize, smem_l2);

    dim3 gKNN(NN / 16, BB);                       // 2048 blocks, warp-per-query
    knn_kernel   <<<gKNN, 512, smem_knn>>>(feats);
    dim3 gL1(NN / 256, BB);
    layer1_kernel<<<gL1, 256, smem_l1>>>(feats, W1, b1);
    layer2_kernel<<<(BB * NN) / PTS, 256, smem_l2>>>(W2, b2, Wf, bf, out);
}

// round 5
// speedup vs baseline: 2.1353x; 1.1807x over previous
#include <cuda_runtime.h>

#define BB   8
#define NN   4096
#define CC   6
#define KNBR 16
#define H1   64
#define H2   128

static __device__ int   g_nbr[BB * NN * KNBR];          // 2 MB
static __device__ float g_x1 [BB * NN * H1];            // 8 MB

#define FINF __int_as_float(0x7f800000)

// ---------------------------------------------------------------------------
// Kernel 1: exact KNN (k=16). Warp handles TWO queries; each query's top-16
// is lane-distributed as (float d2, int idx), kept sorted by stable
// warp-cooperative insertion (candidates processed in increasing index =>
// strict '<' compares give lower-index-wins ties, matching lax.top_k).
// d2 bit-matches reference: d2 = fma(dot, -2, sq_i + sq_j), ascending fma dot.
// ---------------------------------------------------------------------------
__global__ __launch_bounds__(512)
void knn_kernel(const float* __restrict__ feats) {
    extern __shared__ float smem_f[];
    float4* sp = (float4*)smem_f;                       // [NN] : x,y,z,sq

    const int b = blockIdx.y;
    const float* fb = feats + (size_t)b * NN * CC;
    for (int j = threadIdx.x; j < NN; j += blockDim.x) {
        float x = fb[j * CC + 0];
        float y = fb[j * CC + 1];
        float z = fb[j * CC + 2];
        float sq = __fadd_rn(__fadd_rn(__fmul_rn(x, x), __fmul_rn(y, y)),
                             __fmul_rn(z, z));
        sp[j] = make_float4(x, y, z, sq);
    }
    __syncthreads();

    const int lane = threadIdx.x & 31;
    const int wid  = threadIdx.x >> 5;                  // 16 warps
    const int i0   = blockIdx.x * 32 + wid * 2;         // query pair
    const int i1   = i0 + 1;
    const float4 qa = sp[i0];
    const float4 qb = sp[i1];
    const int diag  = i0 & ~31;                         // shared diagonal block
    const int la    = i0 & 31;
    const int lb    = i1 & 31;

    float bda = FINF, bdb = FINF;                       // lane-distributed lists
    int   bia = 0,    bib = 0;
    float taua = FINF, taub = FINF;

#pragma unroll 2
    for (int jb = 0; jb < NN; jb += 32) {
        const float4 p = sp[jb + lane];
        const int jidx = jb + lane;

        float dota = __fmaf_rn(qa.z, p.z, __fmaf_rn(qa.y, p.y, __fmul_rn(qa.x, p.x)));
        float d2a  = __fmaf_rn(dota, -2.0f, __fadd_rn(qa.w, p.w));
        float dotb = __fmaf_rn(qb.z, p.z, __fmaf_rn(qb.y, p.y, __fmul_rn(qb.x, p.x)));
        float d2b  = __fmaf_rn(dotb, -2.0f, __fadd_rn(qb.w, p.w));

        if (jb == diag) {                               // warp-uniform branch
            if (lane == la) d2a = FINF;                 // exclude self
            if (lane == lb) d2b = FINF;
        }

        unsigned bal = __ballot_sync(0xFFFFFFFFu, d2a < taua);
        while (bal) {
            int src = __ffs(bal) - 1;
            bal &= bal - 1;
            float nd = __shfl_sync(0xFFFFFFFFu, d2a, src);
            int   ni = __shfl_sync(0xFFFFFFFFu, jidx, src);
            unsigned m = __ballot_sync(0xFFFFFFFFu, nd < bda);
            float ud = __shfl_up_sync(0xFFFFFFFFu, bda, 1);
            int   ui = __shfl_up_sync(0xFFFFFFFFu, bia, 1);
            if (m) {
                int pos = __ffs(m) - 1;
                if (lane >= pos) {
                    bda = (lane == pos) ? nd : ud;
                    bia = (lane == pos) ? ni : ui;
                }
            }
            taua = __shfl_sync(0xFFFFFFFFu, bda, 15);
            if (bal) bal &= __ballot_sync(0xFFFFFFFFu, d2a < taua);
        }

        bal = __ballot_sync(0xFFFFFFFFu, d2b < taub);
        while (bal) {
            int src = __ffs(bal) - 1;
            bal &= bal - 1;
            float nd = __shfl_sync(0xFFFFFFFFu, d2b, src);
            int   ni = __shfl_sync(0xFFFFFFFFu, jidx, src);
            unsigned m = __ballot_sync(0xFFFFFFFFu, nd < bdb);
            float ud = __shfl_up_sync(0xFFFFFFFFu, bdb, 1);
            int   ui = __shfl_up_sync(0xFFFFFFFFu, bib, 1);
            if (m) {
                int pos = __ffs(m) - 1;
                if (lane >= pos) {
                    bdb = (lane == pos) ? nd : ud;
                    bib = (lane == pos) ? ni : ui;
                }
            }
            taub = __shfl_sync(0xFFFFFFFFu, bdb, 15);
            if (bal) bal &= __ballot_sync(0xFFFFFFFFu, d2b < taub);
        }
    }

    if (lane < KNBR) {
        g_nbr[(b * NN + i0) * KNBR + lane] = bia;
        g_nbr[(b * NN + i1) * KNBR + lane] = bib;
    }
}

// ---------------------------------------------------------------------------
// Kernel 2: x1 = relu( ((sum_{j in nbr(i)} feats[j]) + feats[i]) @ W1 * inv + b1 )
// ---------------------------------------------------------------------------
__global__ void layer1_kernel(const float* __restrict__ feats,
                              const float* __restrict__ W1,
                              const float* __restrict__ b1) {
    extern __shared__ float smem_f[];
    float* fs  = smem_f;                // NN*CC
    float* W1s = fs + NN * CC;          // CC*H1
    float* b1s = W1s + CC * H1;         // H1

    const int b = blockIdx.y;
    const float* fb = feats + (size_t)b * NN * CC;
    for (int t = threadIdx.x; t < NN * CC; t += blockDim.x) fs[t] = fb[t];
    for (int t = threadIdx.x; t < CC * H1; t += blockDim.x) W1s[t] = W1[t];
    if (threadIdx.x < H1) b1s[threadIdx.x] = b1[threadIdx.x];
    __syncthreads();

    const int i = blockIdx.x * blockDim.x + threadIdx.x;

    float s[CC];
#pragma unroll
    for (int c = 0; c < CC; ++c) s[c] = fs[i * CC + c];

    const int* nb = g_nbr + (size_t)(b * NN + i) * KNBR;
#pragma unroll
    for (int n = 0; n < KNBR; ++n) {
        int j = nb[n];
#pragma unroll
        for (int c = 0; c < CC; ++c) s[c] += fs[j * CC + c];
    }

    float* xo = g_x1 + (size_t)(b * NN + i) * H1;
    const float inv = 1.0f / 17.0f;
#pragma unroll 4
    for (int c = 0; c < H1; ++c) {
        float a = s[0] * W1s[c];
#pragma unroll
        for (int kk = 1; kk < CC; ++kk) a = fmaf(s[kk], W1s[kk * H1 + c], a);
        xo[c] = fmaxf(fmaf(a, inv, b1s[c]), 0.0f);
    }
}

// ---------------------------------------------------------------------------
// Kernel 3 (fused): gather-sum x1 -> x2 = relu(.@W2*inv+b2) -> out = x2@Wf+bf
// 512 threads / 64 points per block (4 warps/SMSP for FFMA latency slack).
// ---------------------------------------------------------------------------
__device__ __forceinline__ float f4get(float4 v, int kk) {
    return kk == 0 ? v.x : kk == 1 ? v.y : kk == 2 ? v.z : v.w;
}

#define PTS 64

__global__ __launch_bounds__(512, 1)
void layer2_kernel(const float* __restrict__ W2,
                   const float* __restrict__ b2,
                   const float* __restrict__ Wf,
                   const float* __restrict__ bf,
                   float* __restrict__ out) {
    extern __shared__ float smem_f[];
    float* W2s = smem_f;                 // 64*128
    float* Wfs = W2s + H1 * H2;          // 128*128
    float* b2s = Wfs + H2 * H2;          // 128
    float* bfs = b2s + H2;               // 128
    float* s1  = bfs + H2;               // PTS*64
    float* x2s = s1 + PTS * H1;          // PTS*128

    for (int t = threadIdx.x; t < H1 * H2; t += blockDim.x) W2s[t] = W2[t];
    for (int t = threadIdx.x; t < H2 * H2; t += blockDim.x) Wfs[t] = Wf[t];
    if (threadIdx.x < H2) { b2s[threadIdx.x] = b2[threadIdx.x]; bfs[threadIdx.x] = bf[threadIdx.x]; }

    const int lane = threadIdx.x & 31;
    const int warp = threadIdx.x >> 5;              // 16 warps
    const int gp0  = blockIdx.x * PTS;              // global point base
    const int b    = gp0 >> 12;                     // / 4096 (PTS divides NN)
    const float* x1b = g_x1 + (size_t)b * NN * H1;

    // phase 1: gather-sum x1 -> s1 (warp w handles points 4w..4w+3)
#pragma unroll
    for (int pp = 0; pp < 4; ++pp) {
        int p  = warp * 4 + pp;
        int gi = gp0 + p;
        int li = gi & (NN - 1);
        const int* nb = g_nbr + (size_t)gi * KNBR;
        float2 v = ((const float2*)(x1b + (size_t)li * H1))[lane];
        float a0 = v.x, a1 = v.y;
#pragma unroll
        for (int n = 0; n < KNBR; ++n) {
            int j = nb[n];
            float2 w = ((const float2*)(x1b + (size_t)j * H1))[lane];
            a0 += w.x; a1 += w.y;
        }
        ((float2*)(s1 + p * H1))[lane] = make_float2(a0, a1);
    }
    __syncthreads();

    const float inv = 1.0f / 17.0f;

    // phase 2: x2 = relu(s1 @ W2 * inv + b2); cols lane*4..lane*4+3
    {
        float acc[4][4];
#pragma unroll
        for (int pp = 0; pp < 4; ++pp)
#pragma unroll
            for (int cc = 0; cc < 4; ++cc) acc[pp][cc] = 0.0f;

#pragma unroll 4
        for (int k = 0; k < H1; k += 4) {
            float4 xv[4];
#pragma unroll
            for (int pp = 0; pp < 4; ++pp)
                xv[pp] = *(const float4*)&s1[(warp * 4 + pp) * H1 + k];
#pragma unroll
            for (int kk = 0; kk < 4; ++kk) {
                float4 w = *(const float4*)&W2s[(k + kk) * H2 + lane * 4];
#pragma unroll
                for (int pp = 0; pp < 4; ++pp) {
                    float xs = f4get(xv[pp], kk);
                    acc[pp][0] = fmaf(xs, w.x, acc[pp][0]);
                    acc[pp][1] = fmaf(xs, w.y, acc[pp][1]);
                    acc[pp][2] = fmaf(xs, w.z, acc[pp][2]);
                    acc[pp][3] = fmaf(xs, w.w, acc[pp][3]);
                }
            }
        }
#pragma unroll
        for (int pp = 0; pp < 4; ++pp) {
            float4 r;
            r.x = fmaxf(fmaf(acc[pp][0], inv, b2s[lane * 4 + 0]), 0.0f);
            r.y = fmaxf(fmaf(acc[pp][1], inv, b2s[lane * 4 + 1]), 0.0f);
            r.z = fmaxf(fmaf(acc[pp][2], inv, b2s[lane * 4 + 2]), 0.0f);
            r.w = fmaxf(fmaf(acc[pp][3], inv, b2s[lane * 4 + 3]), 0.0f);
            *(float4*)&x2s[(warp * 4 + pp) * H2 + lane * 4] = r;
        }
    }
    __syncthreads();

    // phase 3: out = x2 @ Wf + bf
    {
        float acc[4][4];
#pragma unroll
        for (int pp = 0; pp < 4; ++pp)
#pragma unroll
            for (int cc = 0; cc < 4; ++cc) acc[pp][cc] = 0.0f;

#pragma unroll 4
        for (int k = 0; k < H2; k += 4) {
            float4 xv[4];
#pragma unroll
            for (int pp = 0; pp < 4; ++pp)
                xv[pp] = *(const float4*)&x2s[(warp * 4 + pp) * H2 + k];
#pragma unroll
            for (int kk = 0; kk < 4; ++kk) {
                float4 w = *(const float4*)&Wfs[(k + kk) * H2 + lane * 4];
#pragma unroll
                for (int pp = 0; pp < 4; ++pp) {
                    float xs = f4get(xv[pp], kk);
                    acc[pp][0] = fmaf(xs, w.x, acc[pp][0]);
                    acc[pp][1] = fmaf(xs, w.y, acc[pp][1]);
                    acc[pp][2] = fmaf(xs, w.z, acc[pp][2]);
                    acc[pp][3] = fmaf(xs, w.w, acc[pp][3]);
                }
            }
        }
#pragma unroll
        for (int pp = 0; pp < 4; ++pp) {
            int gi = gp0 + warp * 4 + pp;
            float4 r;
            r.x = acc[pp][0] + bfs[lane * 4 + 0];
            r.y = acc[pp][1] + bfs[lane * 4 + 1];
            r.z = acc[pp][2] + bfs[lane * 4 + 2];
            r.w = acc[pp][3] + bfs[lane * 4 + 3];
            *(float4*)&out[(size_t)gi * H2 + lane * 4] = r;
        }
    }
}

// ---------------------------------------------------------------------------
extern "C" void kernel_launch(void* const* d_in, const int* in_sizes, int n_in,
                              void* d_out, int out_size) {
    const float* feats = (const float*)d_in[0];
    const float* W1    = (const float*)d_in[1];
    const float* b1    = (const float*)d_in[2];
    const float* W2    = (const float*)d_in[3];
    const float* b2    = (const float*)d_in[4];
    const float* Wf    = (const float*)d_in[5];
    const float* bf    = (const float*)d_in[6];
    float* out = (float*)d_out;

    const int smem_knn = NN * (int)sizeof(float4);                       // 64 KB
    const int smem_l1  = (NN * CC + CC * H1 + H1) * (int)sizeof(float);  // ~98 KB
    const int smem_l2  = (H1 * H2 + H2 * H2 + 2 * H2 + PTS * H1 + PTS * H2)
                         * (int)sizeof(float);                           // ~145 KB

    cudaFuncSetAttribute(knn_kernel,    cudaFuncAttributeMaxDynamicSharedMemorySize, smem_knn);
    cudaFuncSetAttribute(layer1_kernel, cudaFuncAttributeMaxDynamicSharedMemorySize, smem_l1);
    cudaFuncSetAttribute(layer2_kernel, cudaFuncAttributeMaxDynamicSharedMemorySize, smem_l2);

    dim3 gKNN(NN / 32, BB);                       // 2 queries/warp, 16 warps/block
    knn_kernel   <<<gKNN, 512, smem_knn>>>(feats);
    dim3 gL1(NN / 256, BB);
    layer1_kernel<<<gL1, 256, smem_l1>>>(feats, W1, b1);
    layer2_kernel<<<(BB * NN) / PTS, 512, smem_l2>>>(W2, b2, Wf, bf, out);
}

// round 6
// speedup vs baseline: 2.2840x; 1.0696x over previous
#include <cuda_runtime.h>

#define BB   8
#define NN   4096
#define CC   6
#define KNBR 16
#define H1   64
#define H2   128

static __device__ int   g_nbr[BB * NN * KNBR];          // 2 MB
static __device__ float g_x1 [BB * NN * H1];            // 8 MB

#define FULLM 0xFFFFFFFFu

// ---------------------------------------------------------------------------
// Kernel 1: exact KNN (k=16). Warp = 2 queries; each query's top-17 is
// lane-distributed (lanes 0..16 sorted ascending; lane 0 ends up = self since
// d2(self) rounds to ~0, far below any real neighbor). Warm start: bitonic
// sort of block-0 candidates. Events: stable warp insertion, straight-line.
// d2 bit-matches reference: d2 = fma(dot,-2, sq_i+sq_j), ascending fma dot.
// ---------------------------------------------------------------------------
__global__ __launch_bounds__(512)
void knn_kernel(const float* __restrict__ feats) {
    extern __shared__ float smem_f[];
    float4* sp = (float4*)smem_f;                       // [NN] : x,y,z,sq

    const int b = blockIdx.y;
    const float* fb = feats + (size_t)b * NN * CC;
    for (int j = threadIdx.x; j < NN; j += blockDim.x) {
        float x = fb[j * CC + 0];
        float y = fb[j * CC + 1];
        float z = fb[j * CC + 2];
        float sq = __fadd_rn(__fadd_rn(__fmul_rn(x, x), __fmul_rn(y, y)),
                             __fmul_rn(z, z));
        sp[j] = make_float4(x, y, z, sq);
    }
    __syncthreads();

    const int lane = threadIdx.x & 31;
    const int wid  = threadIdx.x >> 5;                  // 16 warps
    const int i0   = blockIdx.x * 32 + wid * 2;
    const int i1   = i0 + 1;
    const float4 qa = sp[i0];
    const float4 qb = sp[i1];

    // ---- warm start: sort block-0's 32 candidates per query ----
    float bda, bdb;
    int   bia, bib;
    {
        float4 p = sp[lane];
        float dota = __fmaf_rn(qa.z, p.z, __fmaf_rn(qa.y, p.y, __fmul_rn(qa.x, p.x)));
        bda = __fmaf_rn(dota, -2.0f, __fadd_rn(qa.w, p.w));
        float dotb = __fmaf_rn(qb.z, p.z, __fmaf_rn(qb.y, p.y, __fmul_rn(qb.x, p.x)));
        bdb = __fmaf_rn(dotb, -2.0f, __fadd_rn(qb.w, p.w));
        bia = lane; bib = lane;

#pragma unroll
        for (int k = 2; k <= 32; k <<= 1) {
#pragma unroll
            for (int j = k >> 1; j > 0; j >>= 1) {
                bool takeSmall = ((lane & k) == 0) == ((lane & j) == 0);
                {
                    float od = __shfl_xor_sync(FULLM, bda, j);
                    int   oi = __shfl_xor_sync(FULLM, bia, j);
                    bool oLess = (od < bda) || (od == bda && oi < bia);
                    if (takeSmall == oLess) { bda = od; bia = oi; }
                }
                {
                    float od = __shfl_xor_sync(FULLM, bdb, j);
                    int   oi = __shfl_xor_sync(FULLM, bib, j);
                    bool oLess = (od < bdb) || (od == bdb && oi < bib);
                    if (takeSmall == oLess) { bdb = od; bib = oi; }
                }
            }
        }
    }
    float taua = __shfl_sync(FULLM, bda, 16);
    float taub = __shfl_sync(FULLM, bdb, 16);

    // ---- main scan ----
#pragma unroll 2
    for (int jb = 32; jb < NN; jb += 32) {
        const float4 p = sp[jb + lane];
        float dota = __fmaf_rn(qa.z, p.z, __fmaf_rn(qa.y, p.y, __fmul_rn(qa.x, p.x)));
        float d2a  = __fmaf_rn(dota, -2.0f, __fadd_rn(qa.w, p.w));
        float dotb = __fmaf_rn(qb.z, p.z, __fmaf_rn(qb.y, p.y, __fmul_rn(qb.x, p.x)));
        float d2b  = __fmaf_rn(dotb, -2.0f, __fadd_rn(qb.w, p.w));

        unsigned balA = __ballot_sync(FULLM, d2a < taua);
        unsigned balB = __ballot_sync(FULLM, d2b < taub);

        while (balA | balB) {
            int srcA = __ffs(balA) - 1;
            int srcB = __ffs(balB) - 1;
            float ndA = __shfl_sync(FULLM, d2a, srcA & 31);
            float ndB = __shfl_sync(FULLM, d2b, srcB & 31);
            int   niA = jb + srcA;
            int   niB = jb + srcB;
            unsigned mA = __ballot_sync(FULLM, balA && (ndA < bda));
            unsigned mB = __ballot_sync(FULLM, balB && (ndB < bdb));
            float udA = __shfl_up_sync(FULLM, bda, 1);
            int   uiA = __shfl_up_sync(FULLM, bia, 1);
            float udB = __shfl_up_sync(FULLM, bdb, 1);
            int   uiB = __shfl_up_sync(FULLM, bib, 1);
            if (mA) {                                   // uniform branch
                int pa = __ffs(mA) - 1;
                if (lane >= pa) { bda = (lane == pa) ? ndA : udA;
                                  bia = (lane == pa) ? niA : uiA; }
            }
            if (mB) {
                int pb = __ffs(mB) - 1;
                if (lane >= pb) { bdb = (lane == pb) ? ndB : udB;
                                  bib = (lane == pb) ? niB : uiB; }
            }
            taua = __shfl_sync(FULLM, bda, 16);
            taub = __shfl_sync(FULLM, bdb, 16);
            balA &= balA - 1;
            balB &= balB - 1;
            balA &= __ballot_sync(FULLM, d2a < taua);
            balB &= __ballot_sync(FULLM, d2b < taub);
        }
    }

    if (lane >= 1 && lane < 17) {                       // lane 0 == self
        g_nbr[(b * NN + i0) * KNBR + lane - 1] = bia;
        g_nbr[(b * NN + i1) * KNBR + lane - 1] = bib;
    }
}

// ---------------------------------------------------------------------------
// Kernel 2: x1 = relu( ((sum_{j in nbr(i)} feats[j]) + feats[i]) @ W1 * inv + b1 )
// ---------------------------------------------------------------------------
__global__ void layer1_kernel(const float* __restrict__ feats,
                              const float* __restrict__ W1,
                              const float* __restrict__ b1) {
    extern __shared__ float smem_f[];
    float* fs  = smem_f;                // NN*CC
    float* W1s = fs + NN * CC;          // CC*H1
    float* b1s = W1s + CC * H1;         // H1

    const int b = blockIdx.y;
    const float* fb = feats + (size_t)b * NN * CC;
    for (int t = threadIdx.x; t < NN * CC; t += blockDim.x) fs[t] = fb[t];
    for (int t = threadIdx.x; t < CC * H1; t += blockDim.x) W1s[t] = W1[t];
    if (threadIdx.x < H1) b1s[threadIdx.x] = b1[threadIdx.x];
    __syncthreads();

    const int i = blockIdx.x * blockDim.x + threadIdx.x;

    float s[CC];
#pragma unroll
    for (int c = 0; c < CC; ++c) s[c] = fs[i * CC + c];

    const int* nb = g_nbr + (size_t)(b * NN + i) * KNBR;
#pragma unroll
    for (int n = 0; n < KNBR; ++n) {
        int j = nb[n];
#pragma unroll
        for (int c = 0; c < CC; ++c) s[c] += fs[j * CC + c];
    }

    float* xo = g_x1 + (size_t)(b * NN + i) * H1;
    const float inv = 1.0f / 17.0f;
#pragma unroll 4
    for (int c = 0; c < H1; ++c) {
        float a = s[0] * W1s[c];
#pragma unroll
        for (int kk = 1; kk < CC; ++kk) a = fmaf(s[kk], W1s[kk * H1 + c], a);
        xo[c] = fmaxf(fmaf(a, inv, b1s[c]), 0.0f);
    }
}

// ---------------------------------------------------------------------------
// Kernel 3 (fused): gather-sum x1 -> x2 = relu(.@W2*inv+b2) -> out = x2@Wf+bf
// ---------------------------------------------------------------------------
__device__ __forceinline__ float f4get(float4 v, int kk) {
    return kk == 0 ? v.x : kk == 1 ? v.y : kk == 2 ? v.z : v.w;
}

#define PTS 64

__global__ __launch_bounds__(512, 1)
void layer2_kernel(const float* __restrict__ W2,
                   const float* __restrict__ b2,
                   const float* __restrict__ Wf,
                   const float* __restrict__ bf,
                   float* __restrict__ out) {
    extern __shared__ float smem_f[];
    float* W2s = smem_f;                 // 64*128
    float* Wfs = W2s + H1 * H2;          // 128*128
    float* b2s = Wfs + H2 * H2;          // 128
    float* bfs = b2s + H2;               // 128
    float* s1  = bfs + H2;               // PTS*64
    float* x2s = s1 + PTS * H1;          // PTS*128

    for (int t = threadIdx.x; t < H1 * H2; t += blockDim.x) W2s[t] = W2[t];
    for (int t = threadIdx.x; t < H2 * H2; t += blockDim.x) Wfs[t] = Wf[t];
    if (threadIdx.x < H2) { b2s[threadIdx.x] = b2[threadIdx.x]; bfs[threadIdx.x] = bf[threadIdx.x]; }

    const int lane = threadIdx.x & 31;
    const int warp = threadIdx.x >> 5;              // 16 warps
    const int gp0  = blockIdx.x * PTS;
    const int b    = gp0 >> 12;
    const float* x1b = g_x1 + (size_t)b * NN * H1;

#pragma unroll
    for (int pp = 0; pp < 4; ++pp) {
        int p  = warp * 4 + pp;
        int gi = gp0 + p;
        int li = gi & (NN - 1);
        const int* nb = g_nbr + (size_t)gi * KNBR;
        float2 v = ((const float2*)(x1b + (size_t)li * H1))[lane];
        float a0 = v.x, a1 = v.y;
#pragma unroll
        for (int n = 0; n < KNBR; ++n) {
            int j = nb[n];
            float2 w = ((const float2*)(x1b + (size_t)j * H1))[lane];
            a0 += w.x; a1 += w.y;
        }
        ((float2*)(s1 + p * H1))[lane] = make_float2(a0, a1);
    }
    __syncthreads();

    const float inv = 1.0f / 17.0f;

    {
        float acc[4][4];
#pragma unroll
        for (int pp = 0; pp < 4; ++pp)
#pragma unroll
            for (int cc = 0; cc < 4; ++cc) acc[pp][cc] = 0.0f;

#pragma unroll 4
        for (int k = 0; k < H1; k += 4) {
            float4 xv[4];
#pragma unroll
            for (int pp = 0; pp < 4; ++pp)
                xv[pp] = *(const float4*)&s1[(warp * 4 + pp) * H1 + k];
#pragma unroll
            for (int kk = 0; kk < 4; ++kk) {
                float4 w = *(const float4*)&W2s[(k + kk) * H2 + lane * 4];
#pragma unroll
                for (int pp = 0; pp < 4; ++pp) {
                    float xs = f4get(xv[pp], kk);
                    acc[pp][0] = fmaf(xs, w.x, acc[pp][0]);
                    acc[pp][1] = fmaf(xs, w.y, acc[pp][1]);
                    acc[pp][2] = fmaf(xs, w.z, acc[pp][2]);
                    acc[pp][3] = fmaf(xs, w.w, acc[pp][3]);
                }
            }
        }
#pragma unroll
        for (int pp = 0; pp < 4; ++pp) {
            float4 r;
            r.x = fmaxf(fmaf(acc[pp][0], inv, b2s[lane * 4 + 0]), 0.0f);
            r.y = fmaxf(fmaf(acc[pp][1], inv, b2s[lane * 4 + 1]), 0.0f);
            r.z = fmaxf(fmaf(acc[pp][2], inv, b2s[lane * 4 + 2]), 0.0f);
            r.w = fmaxf(fmaf(acc[pp][3], inv, b2s[lane * 4 + 3]), 0.0f);
            *(float4*)&x2s[(warp * 4 + pp) * H2 + lane * 4] = r;
        }
    }
    __syncthreads();

    {
        float acc[4][4];
#pragma unroll
        for (int pp = 0; pp < 4; ++pp)
#pragma unroll
            for (int cc = 0; cc < 4; ++cc) acc[pp][cc] = 0.0f;

#pragma unroll 4
        for (int k = 0; k < H2; k += 4) {
            float4 xv[4];
#pragma unroll
            for (int pp = 0; pp < 4; ++pp)
                xv[pp] = *(const float4*)&x2s[(warp * 4 + pp) * H2 + k];
#pragma unroll
            for (int kk = 0; kk < 4; ++kk) {
                float4 w = *(const float4*)&Wfs[(k + kk) * H2 + lane * 4];
#pragma unroll
                for (int pp = 0; pp < 4; ++pp) {
                    float xs = f4get(xv[pp], kk);
                    acc[pp][0] = fmaf(xs, w.x, acc[pp][0]);
                    acc[pp][1] = fmaf(xs, w.y, acc[pp][1]);
                    acc[pp][2] = fmaf(xs, w.z, acc[pp][2]);
                    acc[pp][3] = fmaf(xs, w.w, acc[pp][3]);
                }
            }
        }
#pragma unroll
        for (int pp = 0; pp < 4; ++pp) {
            int gi = gp0 + warp * 4 + pp;
            float4 r;
            r.x = acc[pp][0] + bfs[lane * 4 + 0];
            r.y = acc[pp][1] + bfs[lane * 4 + 1];
            r.z = acc[pp][2] + bfs[lane * 4 + 2];
            r.w = acc[pp][3] + bfs[lane * 4 + 3];
            *(float4*)&out[(size_t)gi * H2 + lane * 4] = r;
        }
    }
}

// ---------------------------------------------------------------------------
extern "C" void kernel_launch(void* const* d_in, const int* in_sizes, int n_in,
                              void* d_out, int out_size) {
    const float* feats = (const float*)d_in[0];
    const float* W1    = (const float*)d_in[1];
    const float* b1    = (const float*)d_in[2];
    const float* W2    = (const float*)d_in[3];
    const float* b2    = (const float*)d_in[4];
    const float* Wf    = (const float*)d_in[5];
    const float* bf    = (const float*)d_in[6];
    float* out = (float*)d_out;

    const int smem_knn = NN * (int)sizeof(float4);                       // 64 KB
    const int smem_l1  = (NN * CC + CC * H1 + H1) * (int)sizeof(float);  // ~98 KB
    const int smem_l2  = (H1 * H2 + H2 * H2 + 2 * H2 + PTS * H1 + PTS * H2)
                         * (int)sizeof(float);                           // ~145 KB

    cudaFuncSetAttribute(knn_kernel,    cudaFuncAttributeMaxDynamicSharedMemorySize, smem_knn);
    cudaFuncSetAttribute(layer1_kernel, cudaFuncAttributeMaxDynamicSharedMemorySize, smem_l1);
    cudaFuncSetAttribute(layer2_kernel, cudaFuncAttributeMaxDynamicSharedMemorySize, smem_l2);

    dim3 gKNN(NN / 32, BB);
    knn_kernel   <<<gKNN, 512, smem_knn>>>(feats);
    dim3 gL1(NN / 256, BB);
    layer1_kernel<<<gL1, 256, smem_l1>>>(feats, W1, b1);
    layer2_kernel<<<(BB * NN) / PTS, 512, smem_l2>>>(W2, b2, Wf, bf, out);
}

// round 7
// speedup vs baseline: 2.5162x; 1.1017x over previous
#include <cuda_runtime.h>

#define BB   8
#define NN   4096
#define CC   6
#define KNBR 16
#define H1   64
#define H2   128

static __device__ int   g_nbr[BB * NN * KNBR];          // 2 MB
static __device__ float g_x1 [BB * NN * H1];            // 8 MB

#define FULLM 0xFFFFFFFFu

// ---------------------------------------------------------------------------
// Kernel 1: exact KNN (k=16). Warp = 2 queries; each query's top-17 is
// lane-distributed (lanes 0..16 sorted ascending; lane 0 = self because
// d2(self) rounds to ~0, below any real neighbor distance). Warm start:
// bitonic sort of block-0 candidates. Insert events: per-query loops with
// stable warp insertion; tau (lane-16 threshold) updated once per eventful
// block only — it is a filter, not a correctness input.
// d2 bit-matches reference: d2 = fma(dot,-2, sq_i+sq_j), ascending fma dot.
// ---------------------------------------------------------------------------
__global__ __launch_bounds__(512)
void knn_kernel(const float* __restrict__ feats) {
    extern __shared__ float smem_f[];
    float4* sp = (float4*)smem_f;                       // [NN] : x,y,z,sq

    const int b = blockIdx.y;
    const float* fb = feats + (size_t)b * NN * CC;
    for (int j = threadIdx.x; j < NN; j += blockDim.x) {
        float x = fb[j * CC + 0];
        float y = fb[j * CC + 1];
        float z = fb[j * CC + 2];
        float sq = __fadd_rn(__fadd_rn(__fmul_rn(x, x), __fmul_rn(y, y)),
                             __fmul_rn(z, z));
        sp[j] = make_float4(x, y, z, sq);
    }
    __syncthreads();

    const int lane = threadIdx.x & 31;
    const int wid  = threadIdx.x >> 5;                  // 16 warps
    const int i0   = blockIdx.x * 32 + wid * 2;
    const int i1   = i0 + 1;
    const float4 qa = sp[i0];
    const float4 qb = sp[i1];

    // ---- warm start: bitonic sort of block-0's 32 candidates per query ----
    float bda, bdb;
    int   bia, bib;
    {
        float4 p = sp[lane];
        float dota = __fmaf_rn(qa.z, p.z, __fmaf_rn(qa.y, p.y, __fmul_rn(qa.x, p.x)));
        bda = __fmaf_rn(dota, -2.0f, __fadd_rn(qa.w, p.w));
        float dotb = __fmaf_rn(qb.z, p.z, __fmaf_rn(qb.y, p.y, __fmul_rn(qb.x, p.x)));
        bdb = __fmaf_rn(dotb, -2.0f, __fadd_rn(qb.w, p.w));
        bia = lane; bib = lane;

#pragma unroll
        for (int k = 2; k <= 32; k <<= 1) {
#pragma unroll
            for (int j = k >> 1; j > 0; j >>= 1) {
                bool takeSmall = ((lane & k) == 0) == ((lane & j) == 0);
                {
                    float od = __shfl_xor_sync(FULLM, bda, j);
                    int   oi = __shfl_xor_sync(FULLM, bia, j);
                    bool oLess = (od < bda) || (od == bda && oi < bia);
                    if (takeSmall == oLess) { bda = od; bia = oi; }
                }
                {
                    float od = __shfl_xor_sync(FULLM, bdb, j);
                    int   oi = __shfl_xor_sync(FULLM, bib, j);
                    bool oLess = (od < bdb) || (od == bdb && oi < bib);
                    if (takeSmall == oLess) { bdb = od; bib = oi; }
                }
            }
        }
    }
    float taua = __shfl_sync(FULLM, bda, 16);
    float taub = __shfl_sync(FULLM, bdb, 16);

    // ---- main scan ----
#pragma unroll 2
    for (int jb = 32; jb < NN; jb += 32) {
        const float4 p = sp[jb + lane];
        float dota = __fmaf_rn(qa.z, p.z, __fmaf_rn(qa.y, p.y, __fmul_rn(qa.x, p.x)));
        float d2a  = __fmaf_rn(dota, -2.0f, __fadd_rn(qa.w, p.w));
        float dotb = __fmaf_rn(qb.z, p.z, __fmaf_rn(qb.y, p.y, __fmul_rn(qb.x, p.x)));
        float d2b  = __fmaf_rn(dotb, -2.0f, __fadd_rn(qb.w, p.w));

        unsigned balA = __ballot_sync(FULLM, d2a < taua);
        unsigned balB = __ballot_sync(FULLM, d2b < taub);

        if (balA) {                                     // warp-uniform
            do {
                int src = __ffs(balA) - 1;
                balA &= balA - 1;
                float nd = __shfl_sync(FULLM, d2a, src);
                int   ni = jb + src;
                unsigned m = __ballot_sync(FULLM, nd < bda);
                float ud = __shfl_up_sync(FULLM, bda, 1);
                int   ui = __shfl_up_sync(FULLM, bia, 1);
                if (m) {
                    int pos = __ffs(m) - 1;
                    if (lane >= pos) { bda = (lane == pos) ? nd : ud;
                                       bia = (lane == pos) ? ni : ui; }
                }
            } while (balA);
            taua = __shfl_sync(FULLM, bda, 16);
        }

        if (balB) {
            do {
                int src = __ffs(balB) - 1;
                balB &= balB - 1;
                float nd = __shfl_sync(FULLM, d2b, src);
                int   ni = jb + src;
                unsigned m = __ballot_sync(FULLM, nd < bdb);
                float ud = __shfl_up_sync(FULLM, bdb, 1);
                int   ui = __shfl_up_sync(FULLM, bib, 1);
                if (m) {
                    int pos = __ffs(m) - 1;
                    if (lane >= pos) { bdb = (lane == pos) ? nd : ud;
                                       bib = (lane == pos) ? ni : ui; }
                }
            } while (balB);
            taub = __shfl_sync(FULLM, bdb, 16);
        }
    }

    if (lane >= 1 && lane < 17) {                       // lane 0 == self
        g_nbr[(b * NN + i0) * KNBR + lane - 1] = bia;
        g_nbr[(b * NN + i1) * KNBR + lane - 1] = bib;
    }
}

// ---------------------------------------------------------------------------
// Kernel 2: x1 = relu( ((sum_{j in nbr(i)} feats[j]) + feats[i]) @ W1 * inv + b1 )
// ---------------------------------------------------------------------------
__global__ void layer1_kernel(const float* __restrict__ feats,
                              const float* __restrict__ W1,
                              const float* __restrict__ b1) {
    extern __shared__ float smem_f[];
    float* fs  = smem_f;                // NN*CC
    float* W1s = fs + NN * CC;          // CC*H1
    float* b1s = W1s + CC * H1;         // H1

    const int b = blockIdx.y;
    const float* fb = feats + (size_t)b * NN * CC;
    for (int t = threadIdx.x; t < NN * CC; t += blockDim.x) fs[t] = fb[t];
    for (int t = threadIdx.x; t < CC * H1; t += blockDim.x) W1s[t] = W1[t];
    if (threadIdx.x < H1) b1s[threadIdx.x] = b1[threadIdx.x];
    __syncthreads();

    const int i = blockIdx.x * blockDim.x + threadIdx.x;

    float s[CC];
#pragma unroll
    for (int c = 0; c < CC; ++c) s[c] = fs[i * CC + c];

    const int* nb = g_nbr + (size_t)(b * NN + i) * KNBR;
#pragma unroll
    for (int n = 0; n < KNBR; ++n) {
        int j = nb[n];
#pragma unroll
        for (int c = 0; c < CC; ++c) s[c] += fs[j * CC + c];
    }

    float* xo = g_x1 + (size_t)(b * NN + i) * H1;
    const float inv = 1.0f / 17.0f;
#pragma unroll 4
    for (int c = 0; c < H1; ++c) {
        float a = s[0] * W1s[c];
#pragma unroll
        for (int kk = 1; kk < CC; ++kk) a = fmaf(s[kk], W1s[kk * H1 + c], a);
        xo[c] = fmaxf(fmaf(a, inv, b1s[c]), 0.0f);
    }
}

// ---------------------------------------------------------------------------
// Kernel 3 (fused): gather-sum x1 -> x2 = relu(.@W2*inv+b2) -> out = x2@Wf+bf
// ---------------------------------------------------------------------------
__device__ __forceinline__ float f4get(float4 v, int kk) {
    return kk == 0 ? v.x : kk == 1 ? v.y : kk == 2 ? v.z : v.w;
}

#define PTS 64

__global__ __launch_bounds__(512, 1)
void layer2_kernel(const float* __restrict__ W2,
                   const float* __restrict__ b2,
                   const float* __restrict__ Wf,
                   const float* __restrict__ bf,
                   float* __restrict__ out) {
    extern __shared__ float smem_f[];
    float* W2s = smem_f;                 // 64*128
    float* Wfs = W2s + H1 * H2;          // 128*128
    float* b2s = Wfs + H2 * H2;          // 128
    float* bfs = b2s + H2;               // 128
    float* s1  = bfs + H2;               // PTS*64
    float* x2s = s1 + PTS * H1;          // PTS*128

    for (int t = threadIdx.x; t < H1 * H2; t += blockDim.x) W2s[t] = W2[t];
    for (int t = threadIdx.x; t < H2 * H2; t += blockDim.x) Wfs[t] = Wf[t];
    if (threadIdx.x < H2) { b2s[threadIdx.x] = b2[threadIdx.x]; bfs[threadIdx.x] = bf[threadIdx.x]; }

    const int lane = threadIdx.x & 31;
    const int warp = threadIdx.x >> 5;              // 16 warps
    const int gp0  = blockIdx.x * PTS;
    const int b    = gp0 >> 12;
    const float* x1b = g_x1 + (size_t)b * NN * H1;

#pragma unroll
    for (int pp = 0; pp < 4; ++pp) {
        int p  = warp * 4 + pp;
        int gi = gp0 + p;
        int li = gi & (NN - 1);
        const int* nb = g_nbr + (size_t)gi * KNBR;
        float2 v = ((const float2*)(x1b + (size_t)li * H1))[lane];
        float a0 = v.x, a1 = v.y;
#pragma unroll
        for (int n = 0; n < KNBR; ++n) {
            int j = nb[n];
            float2 w = ((const float2*)(x1b + (size_t)j * H1))[lane];
            a0 += w.x; a1 += w.y;
        }
        ((float2*)(s1 + p * H1))[lane] = make_float2(a0, a1);
    }
    __syncthreads();

    const float inv = 1.0f / 17.0f;

    {
        float acc[4][4];
#pragma unroll
        for (int pp = 0; pp < 4; ++pp)
#pragma unroll
            for (int cc = 0; cc < 4; ++cc) acc[pp][cc] = 0.0f;

#pragma unroll 4
        for (int k = 0; k < H1; k += 4) {
            float4 xv[4];
#pragma unroll
            for (int pp = 0; pp < 4; ++pp)
                xv[pp] = *(const float4*)&s1[(warp * 4 + pp) * H1 + k];
#pragma unroll
            for (int kk = 0; kk < 4; ++kk) {
                float4 w = *(const float4*)&W2s[(k + kk) * H2 + lane * 4];
#pragma unroll
                for (int pp = 0; pp < 4; ++pp) {
                    float xs = f4get(xv[pp], kk);
                    acc[pp][0] = fmaf(xs, w.x, acc[pp][0]);
                    acc[pp][1] = fmaf(xs, w.y, acc[pp][1]);
                    acc[pp][2] = fmaf(xs, w.z, acc[pp][2]);
                    acc[pp][3] = fmaf(xs, w.w, acc[pp][3]);
                }
            }
        }
#pragma unroll
        for (int pp = 0; pp < 4; ++pp) {
            float4 r;
            r.x = fmaxf(fmaf(acc[pp][0], inv, b2s[lane * 4 + 0]), 0.0f);
            r.y = fmaxf(fmaf(acc[pp][1], inv, b2s[lane * 4 + 1]), 0.0f);
            r.z = fmaxf(fmaf(acc[pp][2], inv, b2s[lane * 4 + 2]), 0.0f);
            r.w = fmaxf(fmaf(acc[pp][3], inv, b2s[lane * 4 + 3]), 0.0f);
            *(float4*)&x2s[(warp * 4 + pp) * H2 + lane * 4] = r;
        }
    }
    __syncthreads();

    {
        float acc[4][4];
#pragma unroll
        for (int pp = 0; pp < 4; ++pp)
#pragma unroll
            for (int cc = 0; cc < 4; ++cc) acc[pp][cc] = 0.0f;

#pragma unroll 4
        for (int k = 0; k < H2; k += 4) {
            float4 xv[4];
#pragma unroll
            for (int pp = 0; pp < 4; ++pp)
                xv[pp] = *(const float4*)&x2s[(warp * 4 + pp) * H2 + k];
#pragma unroll
            for (int kk = 0; kk < 4; ++kk) {
                float4 w = *(const float4*)&Wfs[(k + kk) * H2 + lane * 4];
#pragma unroll
                for (int pp = 0; pp < 4; ++pp) {
                    float xs = f4get(xv[pp], kk);
                    acc[pp][0] = fmaf(xs, w.x, acc[pp][0]);
                    acc[pp][1] = fmaf(xs, w.y, acc[pp][1]);
                    acc[pp][2] = fmaf(xs, w.z, acc[pp][2]);
                    acc[pp][3] = fmaf(xs, w.w, acc[pp][3]);
                }
            }
        }
#pragma unroll
        for (int pp = 0; pp < 4; ++pp) {
            int gi = gp0 + warp * 4 + pp;
            float4 r;
            r.x = acc[pp][0] + bfs[lane * 4 + 0];
            r.y = acc[pp][1] + bfs[lane * 4 + 1];
            r.z = acc[pp][2] + bfs[lane * 4 + 2];
            r.w = acc[pp][3] + bfs[lane * 4 + 3];
            *(float4*)&out[(size_t)gi * H2 + lane * 4] = r;
        }
    }
}

// ---------------------------------------------------------------------------
extern "C" void kernel_launch(void* const* d_in, const int* in_sizes, int n_in,
                              void* d_out, int out_size) {
    const float* feats = (const float*)d_in[0];
    const float* W1    = (const float*)d_in[1];
    const float* b1    = (const float*)d_in[2];
    const float* W2    = (const float*)d_in[3];
    const float* b2    = (const float*)d_in[4];
    const float* Wf    = (const float*)d_in[5];
    const float* bf    = (const float*)d_in[6];
    float* out = (float*)d_out;

    const int smem_knn = NN * (int)sizeof(float4);                       // 64 KB
    const int smem_l1  = (NN * CC + CC * H1 + H1) * (int)sizeof(float);  // ~98 KB
    const int smem_l2  = (H1 * H2 + H2 * H2 + 2 * H2 + PTS * H1 + PTS * H2)
                         * (int)sizeof(float);                           // ~145 KB

    cudaFuncSetAttribute(knn_kernel,    cudaFuncAttributeMaxDynamicSharedMemorySize, smem_knn);
    cudaFuncSetAttribute(layer1_kernel, cudaFuncAttributeMaxDynamicSharedMemorySize, smem_l1);
    cudaFuncSetAttribute(layer2_kernel, cudaFuncAttributeMaxDynamicSharedMemorySize, smem_l2);

    dim3 gKNN(NN / 32, BB);
    knn_kernel   <<<gKNN, 512, smem_knn>>>(feats);
    dim3 gL1(NN / 256, BB);
    layer1_kernel<<<gL1, 256, smem_l1>>>(feats, W1, b1);
    layer2_kernel<<<(BB * NN) / PTS, 512, smem_l2>>>(W2, b2, Wf, bf, out);
}